// round 12
// baseline (speedup 1.0000x reference)
#include <cuda_runtime.h>
#include <cuda_bf16.h>
#include <cstdint>

#define MAXN 100000
#define MAXE 1600000
#define DHID 128
#define SCAN_B 1024
#define MAXBLK 128

// ---------------------------------------------------------------------------
// Scratch (device globals; zero-initialized at load, kept consistent across
// graph replays: scan_all re-zeros cnt, fill re-zeros bsums)
// ---------------------------------------------------------------------------
__device__ float g_x1[(size_t)MAXN * DHID];
__device__ float g_x2[(size_t)MAXN * DHID];
__device__ int   g_cnt[MAXN];
__device__ int2  g_rc[MAXN];                 // (rowstart, cnt)
__device__ int   g_cursor[MAXN];
__device__ int   g_bsums[MAXBLK];            // bit31 = ready flag, bits0..30 = sum
__device__ int2  g_colw[MAXE];               // packed (src, w-bits)
// fragment-packed weights: [ks 8][n 128][tig 4] uint4{bh0,bh1,bl0,bl1}
__device__ uint4 g_w1f[4096];
__device__ uint4 g_w2f[4096];

// ---------------------------------------------------------------------------
__device__ __forceinline__ void mma16816(float* c, const uint32_t* a, const uint32_t* bb) {
    asm volatile(
        "mma.sync.aligned.m16n8k16.row.col.f32.bf16.bf16.f32 "
        "{%0,%1,%2,%3}, {%4,%5,%6,%7}, {%8,%9}, {%0,%1,%2,%3};"
        : "+f"(c[0]), "+f"(c[1]), "+f"(c[2]), "+f"(c[3])
        : "r"(a[0]), "r"(a[1]), "r"(a[2]), "r"(a[3]), "r"(bb[0]), "r"(bb[1]));
}

// ---------------------------------------------------------------------------
// CSR build
// ---------------------------------------------------------------------------
__global__ void count_kernel(const int* __restrict__ dst, int* __restrict__ cnt, int E) {
    int e = blockIdx.x * blockDim.x + threadIdx.x;
    if (e < E) atomicAdd(&cnt[dst[e]], 1);
}

__global__ void __launch_bounds__(SCAN_B)
scan_all_kernel(int* __restrict__ cnt, int* __restrict__ bsums,
                int2* __restrict__ rc, int* __restrict__ cursor, int N) {
    __shared__ int s[SCAN_B];
    __shared__ int boff_sh;
    int tid = threadIdx.x;
    int b = blockIdx.x;
    int i = b * SCAN_B + tid;
    int v = 0;
    if (i < N) { v = cnt[i]; cnt[i] = 0; }
    s[tid] = v;
    if (tid == 0) boff_sh = 0;
    __syncthreads();
#pragma unroll
    for (int off = 1; off < SCAN_B; off <<= 1) {
        int t = (tid >= off) ? s[tid - off] : 0;
        __syncthreads();
        s[tid] += t;
        __syncthreads();
    }
    if (tid == SCAN_B - 1)
        *((volatile int*)&bsums[b]) = s[tid] | 0x80000000;
    if (tid < b) {   // b <= 97 < SCAN_B; all 98 blocks co-resident (148 SMs)
        int bv;
        do { bv = *((volatile int*)&bsums[tid]); } while ((bv & 0x80000000) == 0);
        atomicAdd(&boff_sh, bv & 0x7FFFFFFF);
    }
    __syncthreads();
    if (i < N) {
        int rs = boff_sh + s[tid] - v;   // exclusive prefix
        rc[i] = make_int2(rs, v);
        cursor[i] = rs;
    }
}

__global__ void fill_kernel(const int* __restrict__ src, const int* __restrict__ dst,
                            const float* __restrict__ ew,
                            int* __restrict__ cursor, int2* __restrict__ colw,
                            int* __restrict__ bsums, int E) {
    if (blockIdx.x == 0 && threadIdx.x < MAXBLK) bsums[threadIdx.x] = 0;
    int e = blockIdx.x * blockDim.x + threadIdx.x;
    if (e < E) {
        int pos = atomicAdd(&cursor[dst[e]], 1);
        colw[pos] = make_int2(src[e], __float_as_int(ew[e]));
    }
}

// ---------------------------------------------------------------------------
// weight prep: split + fragment-pack.  Fragment (ks, n, tig):
//   bh0 = bf16x2( W[n][ks*16+tig*2], W[n][ks*16+tig*2+1] )   (hi part)
//   bh1 = same at k+8 ;  bl0/bl1 = lo parts
// ---------------------------------------------------------------------------
__device__ __forceinline__ uint32_t pack_hi2(float a, float b,
                                             float& ra, float& rb) {
    __nv_bfloat16 ha = __float2bfloat16(a);
    __nv_bfloat16 hb = __float2bfloat16(b);
    ra = a - __bfloat162float(ha);
    rb = b - __bfloat162float(hb);
    return ((uint32_t)__bfloat16_as_ushort(hb) << 16) | __bfloat16_as_ushort(ha);
}
__device__ __forceinline__ uint32_t pack_lo2(float ra, float rb) {
    __nv_bfloat16 la = __float2bfloat16(ra);
    __nv_bfloat16 lb = __float2bfloat16(rb);
    return ((uint32_t)__bfloat16_as_ushort(lb) << 16) | __bfloat16_as_ushort(la);
}

__global__ void prep_w_kernel(const float* __restrict__ w1, const float* __restrict__ w2) {
    int idx = blockIdx.x * blockDim.x + threadIdx.x;   // 0 .. 8191
    int which = idx >> 12;
    int rem = idx & 4095;
    int ks = rem >> 9;
    int n = (rem >> 2) & 127;
    int tig = rem & 3;
    const float* W = which ? w2 : w1;
    int k0 = ks * 16 + tig * 2;
    float e0 = W[n * 128 + k0],     e1 = W[n * 128 + k0 + 1];
    float e2 = W[n * 128 + k0 + 8], e3 = W[n * 128 + k0 + 9];
    float r0, r1, r2, r3;
    uint4 f;
    f.x = pack_hi2(e0, e1, r0, r1);
    f.y = pack_hi2(e2, e3, r2, r3);
    f.z = pack_lo2(r0, r1);
    f.w = pack_lo2(r2, r3);
    if (which) g_w2f[rem] = f; else g_w1f[rem] = f;
}

// ---------------------------------------------------------------------------
// aggregation + combine:  y = (1+eps)*x + mean over in-edges of x[src]*w
// one warp per node; lane owns 4 features. MLP=2 (empirically optimal).
// ---------------------------------------------------------------------------
__global__ void __launch_bounds__(256)
agg_kernel(const float* __restrict__ x,
           const int2* __restrict__ rc, const int2* __restrict__ colw,
           const float* __restrict__ eps_ptr, int eps_idx,
           float* __restrict__ y, int N) {
    int t = blockIdx.x * blockDim.x + threadIdx.x;
    int node = t >> 5;
    int lane = t & 31;
    if (node >= N) return;

    int2 rcv = __ldg(&rc[node]);
    int start = rcv.x;
    int c = rcv.y;

    float4 a0 = make_float4(0.f, 0.f, 0.f, 0.f);
    float4 a1 = a0;
    int j = 0;
    for (; j + 1 < c; j += 2) {
        int2 e0 = __ldg(&colw[start + j]);
        int2 e1 = __ldg(&colw[start + j + 1]);
        float w0 = __int_as_float(e0.y);
        float w1 = __int_as_float(e1.y);
        float4 v0 = __ldg(reinterpret_cast<const float4*>(x + (size_t)e0.x * DHID) + lane);
        float4 v1 = __ldg(reinterpret_cast<const float4*>(x + (size_t)e1.x * DHID) + lane);
        a0.x += v0.x * w0; a0.y += v0.y * w0; a0.z += v0.z * w0; a0.w += v0.w * w0;
        a1.x += v1.x * w1; a1.y += v1.y * w1; a1.z += v1.z * w1; a1.w += v1.w * w1;
    }
    if (j < c) {
        int2 e0 = __ldg(&colw[start + j]);
        float w0 = __int_as_float(e0.y);
        float4 v0 = __ldg(reinterpret_cast<const float4*>(x + (size_t)e0.x * DHID) + lane);
        a0.x += v0.x * w0; a0.y += v0.y * w0; a0.z += v0.z * w0; a0.w += v0.w * w0;
    }
    float dinv = (c > 0) ? (1.0f / (float)c) : 0.0f;
    float epsv = 1.0f + eps_ptr[eps_idx];

    float4 xv = __ldg(reinterpret_cast<const float4*>(x + (size_t)node * DHID + lane * 4));
    float4 o;
    o.x = epsv * xv.x + (a0.x + a1.x) * dinv;
    o.y = epsv * xv.y + (a0.y + a1.y) * dinv;
    o.z = epsv * xv.z + (a0.z + a1.z) * dinv;
    o.w = epsv * xv.w + (a0.w + a1.w) * dinv;
    *reinterpret_cast<float4*>(y + (size_t)node * DHID + lane * 4) = o;
}

// ---------------------------------------------------------------------------
// HMMA GEMM:  out = y @ W^T + b  [+relu]
// 64-row tiles, 2 CTAs/SM. Fragment-packed smem:
//   A: per row, k-pair p (p=k/2) stored as {hi,lo} uint2 at p*8; pad 544B/row.
//      -> 4 LDS.64 per k-step deliver all 8 A regs (hi+lo).
//   B: [ks][n][tig] uint4{bh0,bh1,bl0,bl1} -> 1 LDS.128 per nt (all 4 B regs).
// Mainloop per thread per k-step: 12 LDS + 24 HMMA (was 40 LDS + 24).
// ---------------------------------------------------------------------------
#define APAD 544
#define SM_A 0
#define SM_B 34816
#define SM_TOT 100352

__global__ void __launch_bounds__(256, 2)
mm_kernel(const float* __restrict__ y, const uint4* __restrict__ wf,
          const float* __restrict__ b,
          float* __restrict__ out, int n_rows, int do_relu, int zero_row0) {
    extern __shared__ __align__(16) char sm[];
    int tid = threadIdx.x;
    int lane = tid & 31;
    int wid = tid >> 5;

    // copy fragment-packed W (4096 uint4 = 64KB)
    {
        uint4* sb = reinterpret_cast<uint4*>(sm + SM_B);
#pragma unroll
        for (int i = 0; i < 16; i++)
            sb[tid + i * 256] = wf[tid + i * 256];
    }

    // A convert: row r, k-chunk kb(32 elems); write {hi,lo} interleaved pairs
    int row0 = blockIdx.x * 64;
    {
        int r = tid >> 2;               // 0..63
        int kb = (tid & 3) * 32;        // 0,32,64,96
        int grow = row0 + r;
        bool valid = (grow < n_rows);
        const float4* yp = reinterpret_cast<const float4*>(y + (size_t)grow * 128 + kb);
        char* arow = sm + SM_A + r * APAD + kb * 4;   // pair p -> +p*8 bytes
#pragma unroll
        for (int j = 0; j < 8; j++) {
            float4 v = valid ? __ldg(yp + j) : make_float4(0.f, 0.f, 0.f, 0.f);
            float r0, r1, r2, r3;
            uint4 q;
            q.x = pack_hi2(v.x, v.y, r0, r1);   // hi pair (k, k+1)
            q.y = pack_lo2(r0, r1);             // lo pair
            q.z = pack_hi2(v.z, v.w, r2, r3);   // hi pair (k+2, k+3)
            q.w = pack_lo2(r2, r3);
            *reinterpret_cast<uint4*>(arow + j * 16) = q;
        }
    }
    __syncthreads();

    int gid = lane >> 2;
    int tig = lane & 3;
    int wr = (wid & 3) * 16;   // warp row base
    int wn = (wid >> 2) * 64;  // warp col base

    const char* pA0 = sm + SM_A + (wr + gid) * APAD + tig * 8;
    const char* pA1 = pA0 + 8 * APAD;

    float acc[8][4];
#pragma unroll
    for (int nt = 0; nt < 8; nt++)
#pragma unroll
        for (int q = 0; q < 4; q++) acc[nt][q] = 0.f;

#pragma unroll
    for (int ks = 0; ks < 8; ks++) {
        int ko = ks * 64;   // 8 pairs * 8B
        uint2 u0 = *reinterpret_cast<const uint2*>(pA0 + ko);        // row g,   k low
        uint2 w0 = *reinterpret_cast<const uint2*>(pA1 + ko);        // row g+8, k low
        uint2 u1 = *reinterpret_cast<const uint2*>(pA0 + ko + 32);   // row g,   k high
        uint2 w1 = *reinterpret_cast<const uint2*>(pA1 + ko + 32);   // row g+8, k high
        uint32_t ahi[4] = {u0.x, w0.x, u1.x, w1.x};
        uint32_t alo[4] = {u0.y, w0.y, u1.y, w1.y};
        const uint4* bks = reinterpret_cast<const uint4*>(sm + SM_B) + (ks * 128 + wn) * 4 + tig;
#pragma unroll
        for (int nt = 0; nt < 8; nt++) {
            uint4 bq = bks[(nt * 8 + gid) * 4];
            uint32_t bh[2] = {bq.x, bq.y};
            uint32_t bl[2] = {bq.z, bq.w};
            mma16816(acc[nt], ahi, bh);
            mma16816(acc[nt], ahi, bl);
            mma16816(acc[nt], alo, bh);
        }
    }

#pragma unroll
    for (int nt = 0; nt < 8; nt++) {
        int colc = wn + nt * 8 + tig * 2;
        float2 bv = *reinterpret_cast<const float2*>(b + colc);
        int ra = row0 + wr + gid;
        float2 o0, o1;
        o0.x = acc[nt][0] + bv.x;
        o0.y = acc[nt][1] + bv.y;
        o1.x = acc[nt][2] + bv.x;
        o1.y = acc[nt][3] + bv.y;
        if (do_relu) {
            o0.x = fmaxf(o0.x, 0.f); o0.y = fmaxf(o0.y, 0.f);
            o1.x = fmaxf(o1.x, 0.f); o1.y = fmaxf(o1.y, 0.f);
        }
        if (zero_row0 && ra == 0) { o0.x = 0.f; o0.y = 0.f; }
        if (ra < n_rows)
            *reinterpret_cast<float2*>(out + (size_t)ra * 128 + colc) = o0;
        if (ra + 8 < n_rows)
            *reinterpret_cast<float2*>(out + (size_t)(ra + 8) * 128 + colc) = o1;
    }
}

// ---------------------------------------------------------------------------
extern "C" void kernel_launch(void* const* d_in, const int* in_sizes, int n_in,
                              void* d_out, int out_size) {
    const float* emb    = (const float*)d_in[0];
    const float* w1     = (const float*)d_in[1];
    const float* b1     = (const float*)d_in[2];
    const float* w2     = (const float*)d_in[3];
    const float* b2     = (const float*)d_in[4];
    const float* eps    = (const float*)d_in[5];
    const float* edge_w = (const float*)d_in[6];
    const int*   src    = (const int*)d_in[7];
    const int*   dst    = (const int*)d_in[8];

    int N = in_sizes[0] / DHID;
    int E = in_sizes[6];
    float* out = (float*)d_out;

    float *x1, *x2;
    int *cnt, *cursor, *bsums;
    int2 *rc, *colw;
    uint4 *w1f, *w2f;
    cudaGetSymbolAddress((void**)&x1, g_x1);
    cudaGetSymbolAddress((void**)&x2, g_x2);
    cudaGetSymbolAddress((void**)&cnt, g_cnt);
    cudaGetSymbolAddress((void**)&rc, g_rc);
    cudaGetSymbolAddress((void**)&cursor, g_cursor);
    cudaGetSymbolAddress((void**)&bsums, g_bsums);
    cudaGetSymbolAddress((void**)&colw, g_colw);
    cudaGetSymbolAddress((void**)&w1f, g_w1f);
    cudaGetSymbolAddress((void**)&w2f, g_w2f);

    static bool attr_set = false;
    if (!attr_set) {
        cudaFuncSetAttribute(mm_kernel,
                             cudaFuncAttributeMaxDynamicSharedMemorySize, SM_TOT);
        attr_set = true;
    }

    int nb = (N + SCAN_B - 1) / SCAN_B;
    int g_edges = (E + 255) / 256;
    int g_agg   = ((size_t)N * 32 + 255) / 256;
    int g_mm    = (N + 63) / 64;

    // ---- CSR build: zero-free (cnt consumed by scan, bsums reset by fill) ----
    count_kernel<<<g_edges, 256>>>(dst, cnt, E);
    scan_all_kernel<<<nb, SCAN_B>>>(cnt, bsums, rc, cursor, N);
    fill_kernel<<<g_edges, 256>>>(src, dst, edge_w, cursor, colw, bsums, E);

    // ---- layer 1: emb -> x1 (relu) ----
    agg_kernel<<<g_agg, 256>>>(emb, rc, colw, eps, 0, x2, N);
    prep_w_kernel<<<32, 256>>>(w1, w2);
    mm_kernel<<<g_mm, 256, SM_TOT>>>(x2, w1f, b1, x1, N, 1, 0);

    // ---- layer 2: x1 -> x2 (relu) ----
    agg_kernel<<<g_agg, 256>>>(x1, rc, colw, eps, 1, x2, N);
    mm_kernel<<<g_mm, 256, SM_TOT>>>(x2, w2f, b2, x1, N, 1, 0);

    // ---- layer 3: x1 -> out (no relu, row 0 zeroed) ----
    agg_kernel<<<g_agg, 256>>>(x1, rc, colw, eps, 2, x2, N);
    mm_kernel<<<g_mm, 256, SM_TOT>>>(x2, w2f, b2, out, N, 0, 1);
}

// round 13
// speedup vs baseline: 1.0408x; 1.0408x over previous
#include <cuda_runtime.h>
#include <cuda_bf16.h>
#include <cstdint>

#define MAXN 100000
#define MAXE 1600000
#define DHID 128
#define SCAN_B 1024
#define MAXBLK 128

// ---------------------------------------------------------------------------
// Scratch (device globals; zero-initialized at load, kept consistent across
// graph replays: scan_all re-zeros cnt, fill re-zeros bsums)
// ---------------------------------------------------------------------------
__device__ float g_x1[(size_t)MAXN * DHID];
__device__ float g_x2[(size_t)MAXN * DHID];
__device__ int   g_cnt[MAXN];
__device__ int2  g_rc[MAXN];                 // (rowstart, cnt)
__device__ int   g_rank[MAXE];               // per-edge rank within its dst
__device__ int   g_bsums[MAXBLK];            // bit31 = ready flag, bits0..30 = sum
__device__ int2  g_colw[MAXE];               // packed (src, w-bits)
// bf16 weight splits, plain row-major [out 128][k 128]
__device__ unsigned short g_w1hi[16384], g_w1lo[16384];
__device__ unsigned short g_w2hi[16384], g_w2lo[16384];

// ---------------------------------------------------------------------------
__device__ __forceinline__ void mma16816(float* c, const uint32_t* a, const uint32_t* bb) {
    asm volatile(
        "mma.sync.aligned.m16n8k16.row.col.f32.bf16.bf16.f32 "
        "{%0,%1,%2,%3}, {%4,%5,%6,%7}, {%8,%9}, {%0,%1,%2,%3};"
        : "+f"(c[0]), "+f"(c[1]), "+f"(c[2]), "+f"(c[3])
        : "r"(a[0]), "r"(a[1]), "r"(a[2]), "r"(a[3]), "r"(bb[0]), "r"(bb[1]));
}

// ---------------------------------------------------------------------------
// CSR build
// ---------------------------------------------------------------------------
// count + per-edge rank: the atomic's return value IS the edge's slot index.
__global__ void count_kernel(const int* __restrict__ dst, int* __restrict__ cnt,
                             int* __restrict__ rank, int E) {
    int e = blockIdx.x * blockDim.x + threadIdx.x;
    if (e < E) rank[e] = atomicAdd(&cnt[dst[e]], 1);
}

__global__ void __launch_bounds__(SCAN_B)
scan_all_kernel(int* __restrict__ cnt, int* __restrict__ bsums,
                int2* __restrict__ rc, int N) {
    __shared__ int s[SCAN_B];
    __shared__ int boff_sh;
    int tid = threadIdx.x;
    int b = blockIdx.x;
    int i = b * SCAN_B + tid;
    int v = 0;
    if (i < N) { v = cnt[i]; cnt[i] = 0; }
    s[tid] = v;
    if (tid == 0) boff_sh = 0;
    __syncthreads();
#pragma unroll
    for (int off = 1; off < SCAN_B; off <<= 1) {
        int t = (tid >= off) ? s[tid - off] : 0;
        __syncthreads();
        s[tid] += t;
        __syncthreads();
    }
    if (tid == SCAN_B - 1)
        *((volatile int*)&bsums[b]) = s[tid] | 0x80000000;
    if (tid < b) {   // b <= 97 < SCAN_B; all 98 blocks co-resident (148 SMs)
        int bv;
        do { bv = *((volatile int*)&bsums[tid]); } while ((bv & 0x80000000) == 0);
        atomicAdd(&boff_sh, bv & 0x7FFFFFFF);
    }
    __syncthreads();
    if (i < N) {
        int rs = boff_sh + s[tid] - v;   // exclusive prefix
        rc[i] = make_int2(rs, v);
    }
}

// atomic-free fill: pos = rowstart[dst] + rank (rc is L2-hot: 800KB)
__global__ void fill_kernel(const int* __restrict__ src, const int* __restrict__ dst,
                            const float* __restrict__ ew,
                            const int2* __restrict__ rc, const int* __restrict__ rank,
                            int2* __restrict__ colw, int* __restrict__ bsums, int E) {
    if (blockIdx.x == 0 && threadIdx.x < MAXBLK) bsums[threadIdx.x] = 0;
    int e = blockIdx.x * blockDim.x + threadIdx.x;
    if (e < E) {
        int d = dst[e];
        int pos = __ldg(&rc[d]).x + rank[e];
        colw[pos] = make_int2(src[e], __float_as_int(ew[e]));
    }
}

// ---------------------------------------------------------------------------
// weight split: W -> hi/lo bf16, plain row-major
// ---------------------------------------------------------------------------
__global__ void prep_w_kernel(const float* __restrict__ w1, const float* __restrict__ w2) {
    int idx = blockIdx.x * blockDim.x + threadIdx.x;   // 0 .. 32767
    int which = idx >> 14;
    int e = idx & 16383;
    float v = (which ? w2 : w1)[e];
    __nv_bfloat16 hb = __float2bfloat16(v);
    __nv_bfloat16 lb = __float2bfloat16(v - __bfloat162float(hb));
    if (which) { g_w2hi[e] = __bfloat16_as_ushort(hb); g_w2lo[e] = __bfloat16_as_ushort(lb); }
    else       { g_w1hi[e] = __bfloat16_as_ushort(hb); g_w1lo[e] = __bfloat16_as_ushort(lb); }
}

// ---------------------------------------------------------------------------
// aggregation + combine:  y = (1+eps)*x + mean over in-edges of x[src]*w
// one warp per node; lane owns 4 features. MLP=2 (empirically optimal).
// ---------------------------------------------------------------------------
__global__ void __launch_bounds__(256)
agg_kernel(const float* __restrict__ x,
           const int2* __restrict__ rc, const int2* __restrict__ colw,
           const float* __restrict__ eps_ptr, int eps_idx,
           float* __restrict__ y, int N) {
    int t = blockIdx.x * blockDim.x + threadIdx.x;
    int node = t >> 5;
    int lane = t & 31;
    if (node >= N) return;

    int2 rcv = __ldg(&rc[node]);
    int start = rcv.x;
    int c = rcv.y;

    float4 a0 = make_float4(0.f, 0.f, 0.f, 0.f);
    float4 a1 = a0;
    int j = 0;
    for (; j + 1 < c; j += 2) {
        int2 e0 = __ldg(&colw[start + j]);
        int2 e1 = __ldg(&colw[start + j + 1]);
        float w0 = __int_as_float(e0.y);
        float w1 = __int_as_float(e1.y);
        float4 v0 = __ldg(reinterpret_cast<const float4*>(x + (size_t)e0.x * DHID) + lane);
        float4 v1 = __ldg(reinterpret_cast<const float4*>(x + (size_t)e1.x * DHID) + lane);
        a0.x += v0.x * w0; a0.y += v0.y * w0; a0.z += v0.z * w0; a0.w += v0.w * w0;
        a1.x += v1.x * w1; a1.y += v1.y * w1; a1.z += v1.z * w1; a1.w += v1.w * w1;
    }
    if (j < c) {
        int2 e0 = __ldg(&colw[start + j]);
        float w0 = __int_as_float(e0.y);
        float4 v0 = __ldg(reinterpret_cast<const float4*>(x + (size_t)e0.x * DHID) + lane);
        a0.x += v0.x * w0; a0.y += v0.y * w0; a0.z += v0.z * w0; a0.w += v0.w * w0;
    }
    float dinv = (c > 0) ? (1.0f / (float)c) : 0.0f;
    float epsv = 1.0f + eps_ptr[eps_idx];

    float4 xv = __ldg(reinterpret_cast<const float4*>(x + (size_t)node * DHID + lane * 4));
    float4 o;
    o.x = epsv * xv.x + (a0.x + a1.x) * dinv;
    o.y = epsv * xv.y + (a0.y + a1.y) * dinv;
    o.z = epsv * xv.z + (a0.z + a1.z) * dinv;
    o.w = epsv * xv.w + (a0.w + a1.w) * dinv;
    *reinterpret_cast<float4*>(y + (size_t)node * DHID + lane * 4) = o;
}

// ---------------------------------------------------------------------------
// HMMA GEMM:  out = y @ W^T + b  [+relu]   (R11-exact, the 401.8us best)
// 64-row tiles, 2 CTAs/SM. fp32 via split: D = Ahi*Bhi + Ahi*Blo + Alo*Bhi.
// ---------------------------------------------------------------------------
#define PADB 272
#define SM_A_HI 0
#define SM_A_LO 17408
#define SM_B_HI 34816
#define SM_B_LO 69632
#define SM_TOT  104448

__device__ __forceinline__ uint32_t pack_hi2(float a, float b,
                                             float& ra, float& rb) {
    __nv_bfloat16 ha = __float2bfloat16(a);
    __nv_bfloat16 hb = __float2bfloat16(b);
    ra = a - __bfloat162float(ha);
    rb = b - __bfloat162float(hb);
    return ((uint32_t)__bfloat16_as_ushort(hb) << 16) | __bfloat16_as_ushort(ha);
}
__device__ __forceinline__ uint32_t pack_lo2(float ra, float rb) {
    __nv_bfloat16 la = __float2bfloat16(ra);
    __nv_bfloat16 lb = __float2bfloat16(rb);
    return ((uint32_t)__bfloat16_as_ushort(lb) << 16) | __bfloat16_as_ushort(la);
}

__global__ void __launch_bounds__(256, 2)
mm_kernel(const float* __restrict__ y,
          const unsigned short* __restrict__ whi, const unsigned short* __restrict__ wlo,
          const float* __restrict__ b,
          float* __restrict__ out, int n_rows, int do_relu, int zero_row0) {
    extern __shared__ __align__(16) char sm[];
    int tid = threadIdx.x;
    int lane = tid & 31;
    int wid = tid >> 5;

    // copy W hi/lo (128 rows x 128 bf16) into padded smem
    {
        const uint4* bh = reinterpret_cast<const uint4*>(whi);
        const uint4* bl = reinterpret_cast<const uint4*>(wlo);
#pragma unroll
        for (int i = 0; i < 8; i++) {
            int idx = tid + i * 256;
            int row = idx >> 4;
            int c = idx & 15;
            *reinterpret_cast<uint4*>(sm + SM_B_HI + row * PADB + c * 16) = bh[idx];
            *reinterpret_cast<uint4*>(sm + SM_B_LO + row * PADB + c * 16) = bl[idx];
        }
    }

    int row0 = blockIdx.x * 64;
    {
        int r = tid >> 2;               // 0..63
        int kb = (tid & 3) * 32;        // 0,32,64,96
        int grow = row0 + r;
        bool valid = (grow < n_rows);
        const float4* yp = reinterpret_cast<const float4*>(y + (size_t)grow * 128 + kb);
#pragma unroll
        for (int j = 0; j < 8; j++) {
            float4 v = valid ? __ldg(yp + j) : make_float4(0.f, 0.f, 0.f, 0.f);
            float r0, r1, r2, r3;
            uint2 hp, lp;
            hp.x = pack_hi2(v.x, v.y, r0, r1);
            hp.y = pack_hi2(v.z, v.w, r2, r3);
            lp.x = pack_lo2(r0, r1);
            lp.y = pack_lo2(r2, r3);
            uint32_t off = (uint32_t)(r * PADB + (kb + j * 4) * 2);
            *reinterpret_cast<uint2*>(sm + SM_A_HI + off) = hp;
            *reinterpret_cast<uint2*>(sm + SM_A_LO + off) = lp;
        }
    }
    __syncthreads();

    int gid = lane >> 2;
    int tig = lane & 3;
    int wr = (wid & 3) * 16;   // warp row base (16 rows)
    int wn = (wid >> 2) * 64;  // warp col base (64 cols)

    const char* pAhi = sm + SM_A_HI + (wr + gid) * PADB + tig * 4;
    const char* pAlo = sm + SM_A_LO + (wr + gid) * PADB + tig * 4;
    const char* pBhi = sm + SM_B_HI + (wn + gid) * PADB + tig * 4;
    const char* pBlo = sm + SM_B_LO + (wn + gid) * PADB + tig * 4;

    float acc[8][4];
#pragma unroll
    for (int nt = 0; nt < 8; nt++)
#pragma unroll
        for (int q = 0; q < 4; q++) acc[nt][q] = 0.f;

#pragma unroll
    for (int k = 0; k < 8; k++) {
        int ko = k * 32;
        uint32_t ahi[4], alo[4];
        ahi[0] = *reinterpret_cast<const uint32_t*>(pAhi + ko);
        ahi[1] = *reinterpret_cast<const uint32_t*>(pAhi + 8 * PADB + ko);
        ahi[2] = *reinterpret_cast<const uint32_t*>(pAhi + ko + 16);
        ahi[3] = *reinterpret_cast<const uint32_t*>(pAhi + 8 * PADB + ko + 16);
        alo[0] = *reinterpret_cast<const uint32_t*>(pAlo + ko);
        alo[1] = *reinterpret_cast<const uint32_t*>(pAlo + 8 * PADB + ko);
        alo[2] = *reinterpret_cast<const uint32_t*>(pAlo + ko + 16);
        alo[3] = *reinterpret_cast<const uint32_t*>(pAlo + 8 * PADB + ko + 16);
#pragma unroll
        for (int nt = 0; nt < 8; nt++) {
            int no = nt * 8 * PADB;
            uint32_t bh[2], bl[2];
            bh[0] = *reinterpret_cast<const uint32_t*>(pBhi + no + ko);
            bh[1] = *reinterpret_cast<const uint32_t*>(pBhi + no + ko + 16);
            bl[0] = *reinterpret_cast<const uint32_t*>(pBlo + no + ko);
            bl[1] = *reinterpret_cast<const uint32_t*>(pBlo + no + ko + 16);
            mma16816(acc[nt], ahi, bh);
            mma16816(acc[nt], ahi, bl);
            mma16816(acc[nt], alo, bh);
        }
    }

#pragma unroll
    for (int nt = 0; nt < 8; nt++) {
        int colc = wn + nt * 8 + tig * 2;
        float2 bv = *reinterpret_cast<const float2*>(b + colc);
        int ra = row0 + wr + gid;
        float2 o0, o1;
        o0.x = acc[nt][0] + bv.x;
        o0.y = acc[nt][1] + bv.y;
        o1.x = acc[nt][2] + bv.x;
        o1.y = acc[nt][3] + bv.y;
        if (do_relu) {
            o0.x = fmaxf(o0.x, 0.f); o0.y = fmaxf(o0.y, 0.f);
            o1.x = fmaxf(o1.x, 0.f); o1.y = fmaxf(o1.y, 0.f);
        }
        if (zero_row0 && ra == 0) { o0.x = 0.f; o0.y = 0.f; }
        if (ra < n_rows)
            *reinterpret_cast<float2*>(out + (size_t)ra * 128 + colc) = o0;
        if (ra + 8 < n_rows)
            *reinterpret_cast<float2*>(out + (size_t)(ra + 8) * 128 + colc) = o1;
    }
}

// ---------------------------------------------------------------------------
extern "C" void kernel_launch(void* const* d_in, const int* in_sizes, int n_in,
                              void* d_out, int out_size) {
    const float* emb    = (const float*)d_in[0];
    const float* w1     = (const float*)d_in[1];
    const float* b1     = (const float*)d_in[2];
    const float* w2     = (const float*)d_in[3];
    const float* b2     = (const float*)d_in[4];
    const float* eps    = (const float*)d_in[5];
    const float* edge_w = (const float*)d_in[6];
    const int*   src    = (const int*)d_in[7];
    const int*   dst    = (const int*)d_in[8];

    int N = in_sizes[0] / DHID;
    int E = in_sizes[6];
    float* out = (float*)d_out;

    float *x1, *x2;
    int *cnt, *bsums, *rank;
    int2 *rc, *colw;
    unsigned short *w1hi, *w1lo, *w2hi, *w2lo;
    cudaGetSymbolAddress((void**)&x1, g_x1);
    cudaGetSymbolAddress((void**)&x2, g_x2);
    cudaGetSymbolAddress((void**)&cnt, g_cnt);
    cudaGetSymbolAddress((void**)&rc, g_rc);
    cudaGetSymbolAddress((void**)&rank, g_rank);
    cudaGetSymbolAddress((void**)&bsums, g_bsums);
    cudaGetSymbolAddress((void**)&colw, g_colw);
    cudaGetSymbolAddress((void**)&w1hi, g_w1hi);
    cudaGetSymbolAddress((void**)&w1lo, g_w1lo);
    cudaGetSymbolAddress((void**)&w2hi, g_w2hi);
    cudaGetSymbolAddress((void**)&w2lo, g_w2lo);

    static bool attr_set = false;
    if (!attr_set) {
        cudaFuncSetAttribute(mm_kernel,
                             cudaFuncAttributeMaxDynamicSharedMemorySize, SM_TOT);
        attr_set = true;
    }

    int nb = (N + SCAN_B - 1) / SCAN_B;
    int g_edges = (E + 255) / 256;
    int g_agg   = ((size_t)N * 32 + 255) / 256;
    int g_mm    = (N + 63) / 64;

    // ---- CSR build: rank-based, atomic-free fill ----
    count_kernel<<<g_edges, 256>>>(dst, cnt, rank, E);
    scan_all_kernel<<<nb, SCAN_B>>>(cnt, bsums, rc, N);
    fill_kernel<<<g_edges, 256>>>(src, dst, edge_w, rc, rank, colw, bsums, E);

    // ---- layer 1: emb -> x1 (relu) ----
    agg_kernel<<<g_agg, 256>>>(emb, rc, colw, eps, 0, x2, N);
    prep_w_kernel<<<128, 256>>>(w1, w2);
    mm_kernel<<<g_mm, 256, SM_TOT>>>(x2, w1hi, w1lo, b1, x1, N, 1, 0);

    // ---- layer 2: x1 -> x2 (relu) ----
    agg_kernel<<<g_agg, 256>>>(x1, rc, colw, eps, 1, x2, N);
    mm_kernel<<<g_mm, 256, SM_TOT>>>(x2, w2hi, w2lo, b2, x1, N, 1, 0);

    // ---- layer 3: x1 -> out (no relu, row 0 zeroed) ----
    agg_kernel<<<g_agg, 256>>>(x1, rc, colw, eps, 2, x2, N);
    mm_kernel<<<g_mm, 256, SM_TOT>>>(x2, w2hi, w2lo, b2, out, N, 0, 1);
}

// round 14
// speedup vs baseline: 1.0503x; 1.0091x over previous
#include <cuda_runtime.h>
#include <cuda_bf16.h>
#include <cstdint>

#define MAXN 100000
#define MAXE 1600000
#define DHID 128
#define SCAN_B 1024
#define MAXBLK 128

// ---------------------------------------------------------------------------
// Scratch (device globals; zero-initialized at load; replay-consistent:
// csr_build consumes cnt, fill resets bsums + sync counter)
// ---------------------------------------------------------------------------
__device__ float g_x1[(size_t)MAXN * DHID];
__device__ float g_x2[(size_t)MAXN * DHID];
__device__ int   g_cnt[MAXN];
__device__ int2  g_rc[MAXN];                 // (rowstart, cnt)
__device__ int   g_rank[MAXE];               // per-edge rank within its dst
__device__ int   g_bsums[MAXBLK];            // bit31 = ready flag, bits0..30 = sum
__device__ int   g_sync[1];                  // grid barrier counter
__device__ int2  g_colw[MAXE];               // packed (src, w-bits)
// bf16 weight splits, plain row-major [out 128][k 128]
__device__ unsigned short g_w1hi[16384], g_w1lo[16384];
__device__ unsigned short g_w2hi[16384], g_w2lo[16384];

// ---------------------------------------------------------------------------
__device__ __forceinline__ void mma16816(float* c, const uint32_t* a, const uint32_t* bb) {
    asm volatile(
        "mma.sync.aligned.m16n8k16.row.col.f32.bf16.bf16.f32 "
        "{%0,%1,%2,%3}, {%4,%5,%6,%7}, {%8,%9}, {%0,%1,%2,%3};"
        : "+f"(c[0]), "+f"(c[1]), "+f"(c[2]), "+f"(c[3])
        : "r"(a[0]), "r"(a[1]), "r"(a[2]), "r"(a[3]), "r"(bb[0]), "r"(bb[1]));
}

__device__ __forceinline__ uint32_t pack_hi2(float a, float b,
                                             float& ra, float& rb) {
    __nv_bfloat16 ha = __float2bfloat16(a);
    __nv_bfloat16 hb = __float2bfloat16(b);
    ra = a - __bfloat162float(ha);
    rb = b - __bfloat162float(hb);
    return ((uint32_t)__bfloat16_as_ushort(hb) << 16) | __bfloat16_as_ushort(ha);
}
__device__ __forceinline__ uint32_t pack_lo2(float ra, float rb) {
    __nv_bfloat16 la = __float2bfloat16(ra);
    __nv_bfloat16 lb = __float2bfloat16(rb);
    return ((uint32_t)__bfloat16_as_ushort(lb) << 16) | __bfloat16_as_ushort(la);
}

// ---------------------------------------------------------------------------
// Fused CSR build: count (+rank) -> grid flag-barrier -> scan, plus W prep.
// 98 blocks x 1024 threads, all co-resident (98 < 148 SMs) -> spin is safe.
// ---------------------------------------------------------------------------
__global__ void __launch_bounds__(SCAN_B)
csr_build_kernel(const int* __restrict__ dst,
                 const float* __restrict__ w1, const float* __restrict__ w2,
                 int* __restrict__ cnt, int* __restrict__ rank,
                 int* __restrict__ bsums, int* __restrict__ sync_ctr,
                 int2* __restrict__ rc, int N, int E, int nblk) {
    __shared__ int s[SCAN_B];
    __shared__ int boff_sh;
    int tid = threadIdx.x;
    int b = blockIdx.x;
    int gt = b * SCAN_B + tid;
    int gsz = nblk * SCAN_B;

    // ---- W prep (first 32768 threads; independent of everything) ----
    if (gt < 32768) {
        int which = gt >> 14;
        int e = gt & 16383;
        float v = (which ? w2 : w1)[e];
        __nv_bfloat16 hb = __float2bfloat16(v);
        __nv_bfloat16 lb = __float2bfloat16(v - __bfloat162float(hb));
        if (which) { g_w2hi[e] = __bfloat16_as_ushort(hb); g_w2lo[e] = __bfloat16_as_ushort(lb); }
        else       { g_w1hi[e] = __bfloat16_as_ushort(hb); g_w1lo[e] = __bfloat16_as_ushort(lb); }
    }

    // ---- phase 1: count + rank (grid-stride) ----
    for (int e = gt; e < E; e += gsz)
        rank[e] = atomicAdd(&cnt[dst[e]], 1);

    // ---- grid barrier (flag counter; all blocks co-resident) ----
    __syncthreads();
    if (tid == 0) {
        __threadfence();
        atomicAdd(sync_ctr, 1);
        while (*((volatile int*)sync_ctr) < nblk) { }
        __threadfence();
    }
    __syncthreads();

    // ---- phase 2: block scan + cross-block offsets (consumes cnt) ----
    int i = gt;
    int v = 0;
    if (i < N) { v = cnt[i]; cnt[i] = 0; }
    s[tid] = v;
    if (tid == 0) boff_sh = 0;
    __syncthreads();
#pragma unroll
    for (int off = 1; off < SCAN_B; off <<= 1) {
        int t = (tid >= off) ? s[tid - off] : 0;
        __syncthreads();
        s[tid] += t;
        __syncthreads();
    }
    if (tid == SCAN_B - 1)
        *((volatile int*)&bsums[b]) = s[tid] | 0x80000000;
    if (tid < b) {   // b <= 97 < SCAN_B
        int bv;
        do { bv = *((volatile int*)&bsums[tid]); } while ((bv & 0x80000000) == 0);
        atomicAdd(&boff_sh, bv & 0x7FFFFFFF);
    }
    __syncthreads();
    if (i < N) {
        int rs = boff_sh + s[tid] - v;
        rc[i] = make_int2(rs, v);
    }
}

// atomic-free fill; also resets bsums + sync counter for the next replay
__global__ void fill_kernel(const int* __restrict__ src, const int* __restrict__ dst,
                            const float* __restrict__ ew,
                            const int2* __restrict__ rc, const int* __restrict__ rank,
                            int2* __restrict__ colw, int* __restrict__ bsums,
                            int* __restrict__ sync_ctr, int E) {
    if (blockIdx.x == 0) {
        if (threadIdx.x < MAXBLK) bsums[threadIdx.x] = 0;
        if (threadIdx.x == 0) *sync_ctr = 0;
    }
    int e = blockIdx.x * blockDim.x + threadIdx.x;
    if (e < E) {
        int d = dst[e];
        int pos = __ldg(&rc[d]).x + rank[e];
        colw[pos] = make_int2(src[e], __float_as_int(ew[e]));
    }
}

// ---------------------------------------------------------------------------
// aggregation + combine:  y = (1+eps)*x + mean over in-edges of x[src]*w
// ---------------------------------------------------------------------------
__global__ void __launch_bounds__(256)
agg_kernel(const float* __restrict__ x,
           const int2* __restrict__ rc, const int2* __restrict__ colw,
           const float* __restrict__ eps_ptr, int eps_idx,
           float* __restrict__ y, int N) {
    int t = blockIdx.x * blockDim.x + threadIdx.x;
    int node = t >> 5;
    int lane = t & 31;
    if (node >= N) return;

    int2 rcv = __ldg(&rc[node]);
    int start = rcv.x;
    int c = rcv.y;

    float4 a0 = make_float4(0.f, 0.f, 0.f, 0.f);
    float4 a1 = a0;
    int j = 0;
    for (; j + 1 < c; j += 2) {
        int2 e0 = __ldg(&colw[start + j]);
        int2 e1 = __ldg(&colw[start + j + 1]);
        float w0 = __int_as_float(e0.y);
        float w1 = __int_as_float(e1.y);
        float4 v0 = __ldg(reinterpret_cast<const float4*>(x + (size_t)e0.x * DHID) + lane);
        float4 v1 = __ldg(reinterpret_cast<const float4*>(x + (size_t)e1.x * DHID) + lane);
        a0.x += v0.x * w0; a0.y += v0.y * w0; a0.z += v0.z * w0; a0.w += v0.w * w0;
        a1.x += v1.x * w1; a1.y += v1.y * w1; a1.z += v1.z * w1; a1.w += v1.w * w1;
    }
    if (j < c) {
        int2 e0 = __ldg(&colw[start + j]);
        float w0 = __int_as_float(e0.y);
        float4 v0 = __ldg(reinterpret_cast<const float4*>(x + (size_t)e0.x * DHID) + lane);
        a0.x += v0.x * w0; a0.y += v0.y * w0; a0.z += v0.z * w0; a0.w += v0.w * w0;
    }
    float dinv = (c > 0) ? (1.0f / (float)c) : 0.0f;
    float epsv = 1.0f + eps_ptr[eps_idx];

    float4 xv = __ldg(reinterpret_cast<const float4*>(x + (size_t)node * DHID + lane * 4));
    float4 o;
    o.x = epsv * xv.x + (a0.x + a1.x) * dinv;
    o.y = epsv * xv.y + (a0.y + a1.y) * dinv;
    o.z = epsv * xv.z + (a0.z + a1.z) * dinv;
    o.w = epsv * xv.w + (a0.w + a1.w) * dinv;
    *reinterpret_cast<float4*>(y + (size_t)node * DHID + lane * 4) = o;
}

// ---------------------------------------------------------------------------
// HMMA GEMM:  out = y @ W^T + b  [+relu]   (R11-exact, the 401.8us best)
// 64-row tiles, 2 CTAs/SM. fp32 via split: D = Ahi*Bhi + Ahi*Blo + Alo*Bhi.
// ---------------------------------------------------------------------------
#define PADB 272
#define SM_A_HI 0
#define SM_A_LO 17408
#define SM_B_HI 34816
#define SM_B_LO 69632
#define SM_TOT  104448

__global__ void __launch_bounds__(256, 2)
mm_kernel(const float* __restrict__ y,
          const unsigned short* __restrict__ whi, const unsigned short* __restrict__ wlo,
          const float* __restrict__ b,
          float* __restrict__ out, int n_rows, int do_relu, int zero_row0) {
    extern __shared__ __align__(16) char sm[];
    int tid = threadIdx.x;
    int lane = tid & 31;
    int wid = tid >> 5;

    {
        const uint4* bh = reinterpret_cast<const uint4*>(whi);
        const uint4* bl = reinterpret_cast<const uint4*>(wlo);
#pragma unroll
        for (int i = 0; i < 8; i++) {
            int idx = tid + i * 256;
            int row = idx >> 4;
            int c = idx & 15;
            *reinterpret_cast<uint4*>(sm + SM_B_HI + row * PADB + c * 16) = bh[idx];
            *reinterpret_cast<uint4*>(sm + SM_B_LO + row * PADB + c * 16) = bl[idx];
        }
    }

    int row0 = blockIdx.x * 64;
    {
        int r = tid >> 2;
        int kb = (tid & 3) * 32;
        int grow = row0 + r;
        bool valid = (grow < n_rows);
        const float4* yp = reinterpret_cast<const float4*>(y + (size_t)grow * 128 + kb);
#pragma unroll
        for (int j = 0; j < 8; j++) {
            float4 v = valid ? __ldg(yp + j) : make_float4(0.f, 0.f, 0.f, 0.f);
            float r0, r1, r2, r3;
            uint2 hp, lp;
            hp.x = pack_hi2(v.x, v.y, r0, r1);
            hp.y = pack_hi2(v.z, v.w, r2, r3);
            lp.x = pack_lo2(r0, r1);
            lp.y = pack_lo2(r2, r3);
            uint32_t off = (uint32_t)(r * PADB + (kb + j * 4) * 2);
            *reinterpret_cast<uint2*>(sm + SM_A_HI + off) = hp;
            *reinterpret_cast<uint2*>(sm + SM_A_LO + off) = lp;
        }
    }
    __syncthreads();

    int gid = lane >> 2;
    int tig = lane & 3;
    int wr = (wid & 3) * 16;
    int wn = (wid >> 2) * 64;

    const char* pAhi = sm + SM_A_HI + (wr + gid) * PADB + tig * 4;
    const char* pAlo = sm + SM_A_LO + (wr + gid) * PADB + tig * 4;
    const char* pBhi = sm + SM_B_HI + (wn + gid) * PADB + tig * 4;
    const char* pBlo = sm + SM_B_LO + (wn + gid) * PADB + tig * 4;

    float acc[8][4];
#pragma unroll
    for (int nt = 0; nt < 8; nt++)
#pragma unroll
        for (int q = 0; q < 4; q++) acc[nt][q] = 0.f;

#pragma unroll
    for (int k = 0; k < 8; k++) {
        int ko = k * 32;
        uint32_t ahi[4], alo[4];
        ahi[0] = *reinterpret_cast<const uint32_t*>(pAhi + ko);
        ahi[1] = *reinterpret_cast<const uint32_t*>(pAhi + 8 * PADB + ko);
        ahi[2] = *reinterpret_cast<const uint32_t*>(pAhi + ko + 16);
        ahi[3] = *reinterpret_cast<const uint32_t*>(pAhi + 8 * PADB + ko + 16);
        alo[0] = *reinterpret_cast<const uint32_t*>(pAlo + ko);
        alo[1] = *reinterpret_cast<const uint32_t*>(pAlo + 8 * PADB + ko);
        alo[2] = *reinterpret_cast<const uint32_t*>(pAlo + ko + 16);
        alo[3] = *reinterpret_cast<const uint32_t*>(pAlo + 8 * PADB + ko + 16);
#pragma unroll
        for (int nt = 0; nt < 8; nt++) {
            int no = nt * 8 * PADB;
            uint32_t bh[2], bl[2];
            bh[0] = *reinterpret_cast<const uint32_t*>(pBhi + no + ko);
            bh[1] = *reinterpret_cast<const uint32_t*>(pBhi + no + ko + 16);
            bl[0] = *reinterpret_cast<const uint32_t*>(pBlo + no + ko);
            bl[1] = *reinterpret_cast<const uint32_t*>(pBlo + no + ko + 16);
            mma16816(acc[nt], ahi, bh);
            mma16816(acc[nt], ahi, bl);
            mma16816(acc[nt], alo, bh);
        }
    }

#pragma unroll
    for (int nt = 0; nt < 8; nt++) {
        int colc = wn + nt * 8 + tig * 2;
        float2 bv = *reinterpret_cast<const float2*>(b + colc);
        int ra = row0 + wr + gid;
        float2 o0, o1;
        o0.x = acc[nt][0] + bv.x;
        o0.y = acc[nt][1] + bv.y;
        o1.x = acc[nt][2] + bv.x;
        o1.y = acc[nt][3] + bv.y;
        if (do_relu) {
            o0.x = fmaxf(o0.x, 0.f); o0.y = fmaxf(o0.y, 0.f);
            o1.x = fmaxf(o1.x, 0.f); o1.y = fmaxf(o1.y, 0.f);
        }
        if (zero_row0 && ra == 0) { o0.x = 0.f; o0.y = 0.f; }
        if (ra < n_rows)
            *reinterpret_cast<float2*>(out + (size_t)ra * 128 + colc) = o0;
        if (ra + 8 < n_rows)
            *reinterpret_cast<float2*>(out + (size_t)(ra + 8) * 128 + colc) = o1;
    }
}

// ---------------------------------------------------------------------------
extern "C" void kernel_launch(void* const* d_in, const int* in_sizes, int n_in,
                              void* d_out, int out_size) {
    const float* emb    = (const float*)d_in[0];
    const float* w1     = (const float*)d_in[1];
    const float* b1     = (const float*)d_in[2];
    const float* w2     = (const float*)d_in[3];
    const float* b2     = (const float*)d_in[4];
    const float* eps    = (const float*)d_in[5];
    const float* edge_w = (const float*)d_in[6];
    const int*   src    = (const int*)d_in[7];
    const int*   dst    = (const int*)d_in[8];

    int N = in_sizes[0] / DHID;
    int E = in_sizes[6];
    float* out = (float*)d_out;

    float *x1, *x2;
    int *cnt, *bsums, *rank, *sync_ctr;
    int2 *rc, *colw;
    unsigned short *w1hi, *w1lo, *w2hi, *w2lo;
    cudaGetSymbolAddress((void**)&x1, g_x1);
    cudaGetSymbolAddress((void**)&x2, g_x2);
    cudaGetSymbolAddress((void**)&cnt, g_cnt);
    cudaGetSymbolAddress((void**)&rc, g_rc);
    cudaGetSymbolAddress((void**)&rank, g_rank);
    cudaGetSymbolAddress((void**)&bsums, g_bsums);
    cudaGetSymbolAddress((void**)&sync_ctr, g_sync);
    cudaGetSymbolAddress((void**)&colw, g_colw);
    cudaGetSymbolAddress((void**)&w1hi, g_w1hi);
    cudaGetSymbolAddress((void**)&w1lo, g_w1lo);
    cudaGetSymbolAddress((void**)&w2hi, g_w2hi);
    cudaGetSymbolAddress((void**)&w2lo, g_w2lo);

    static bool attr_set = false;
    if (!attr_set) {
        cudaFuncSetAttribute(mm_kernel,
                             cudaFuncAttributeMaxDynamicSharedMemorySize, SM_TOT);
        attr_set = true;
    }

    int nb = (N + SCAN_B - 1) / SCAN_B;   // 98 blocks, all co-resident
    int g_edges = (E + 255) / 256;
    int g_agg   = ((size_t)N * 32 + 255) / 256;
    int g_mm    = (N + 63) / 64;

    // ---- CSR build + W prep in ONE kernel; fill resets barrier state ----
    csr_build_kernel<<<nb, SCAN_B>>>(dst, w1, w2, cnt, rank, bsums, sync_ctr,
                                     rc, N, E, nb);                         // 1
    fill_kernel<<<g_edges, 256>>>(src, dst, edge_w, rc, rank, colw,
                                  bsums, sync_ctr, E);                      // 2

    // ---- layer 1 ----
    agg_kernel<<<g_agg, 256>>>(emb, rc, colw, eps, 0, x2, N);               // 3
    mm_kernel<<<g_mm, 256, SM_TOT>>>(x2, w1hi, w1lo, b1, x1, N, 1, 0);      // 4 <- ncu

    // ---- layer 2 ----
    agg_kernel<<<g_agg, 256>>>(x1, rc, colw, eps, 1, x2, N);
    mm_kernel<<<g_mm, 256, SM_TOT>>>(x2, w2hi, w2lo, b2, x1, N, 1, 0);

    // ---- layer 3 ----
    agg_kernel<<<g_agg, 256>>>(x1, rc, colw, eps, 2, x2, N);
    mm_kernel<<<g_mm, 256, SM_TOT>>>(x2, w2hi, w2lo, b2, out, N, 0, 1);
}

// round 15
// speedup vs baseline: 1.1516x; 1.0964x over previous
#include <cuda_runtime.h>
#include <cuda_fp16.h>
#include <cstdint>

#define MAXN 100000
#define MAXE 1600000
#define DHID 128
#define SCAN_B 1024
#define MAXBLK 128

// ---------------------------------------------------------------------------
// Scratch (device globals; zero-initialized at load; replay-consistent:
// csr_build consumes cnt, fill resets bsums + sync counter)
// ---------------------------------------------------------------------------
__device__ float g_x1[(size_t)MAXN * DHID];
__device__ float g_x2[(size_t)MAXN * DHID];
__device__ int   g_cnt[MAXN];
__device__ int2  g_rc[MAXN];                 // (rowstart, cnt)
__device__ int   g_rank[MAXE];               // per-edge rank within its dst
__device__ int   g_bsums[MAXBLK];            // bit31 = ready flag, bits0..30 = sum
__device__ int   g_sync[1];                  // grid barrier counter
__device__ int2  g_colw[MAXE];               // packed (src, w-bits)
// fp16 weights (hi only), row-major [out 128][k 128]
__device__ unsigned short g_w1h[16384];
__device__ unsigned short g_w2h[16384];

// ---------------------------------------------------------------------------
__device__ __forceinline__ void mma_f16(float* c, const uint32_t* a, const uint32_t* bb) {
    asm volatile(
        "mma.sync.aligned.m16n8k16.row.col.f32.f16.f16.f32 "
        "{%0,%1,%2,%3}, {%4,%5,%6,%7}, {%8,%9}, {%0,%1,%2,%3};"
        : "+f"(c[0]), "+f"(c[1]), "+f"(c[2]), "+f"(c[3])
        : "r"(a[0]), "r"(a[1]), "r"(a[2]), "r"(a[3]), "r"(bb[0]), "r"(bb[1]));
}

__device__ __forceinline__ uint32_t pack_h2(float a, float b, float& ra, float& rb) {
    __half ha = __float2half_rn(a);
    __half hb = __float2half_rn(b);
    ra = a - __half2float(ha);
    rb = b - __half2float(hb);
    return ((uint32_t)__half_as_ushort(hb) << 16) | __half_as_ushort(ha);
}
__device__ __forceinline__ uint32_t pack_h2n(float a, float b) {
    __half ha = __float2half_rn(a);
    __half hb = __float2half_rn(b);
    return ((uint32_t)__half_as_ushort(hb) << 16) | __half_as_ushort(ha);
}

// ---------------------------------------------------------------------------
// Fused CSR build: count (+rank) -> grid flag-barrier -> scan, plus W prep.
// 98 blocks x 1024 threads, all co-resident (98 < 148 SMs) -> spin is safe.
// ---------------------------------------------------------------------------
__global__ void __launch_bounds__(SCAN_B)
csr_build_kernel(const int* __restrict__ dst,
                 const float* __restrict__ w1, const float* __restrict__ w2,
                 int* __restrict__ cnt, int* __restrict__ rank,
                 int* __restrict__ bsums, int* __restrict__ sync_ctr,
                 int2* __restrict__ rc, int N, int E, int nblk) {
    __shared__ int s[SCAN_B];
    __shared__ int boff_sh;
    int tid = threadIdx.x;
    int b = blockIdx.x;
    int gt = b * SCAN_B + tid;
    int gsz = nblk * SCAN_B;

    // ---- W prep (first 32768 threads; independent) ----
    if (gt < 32768) {
        int which = gt >> 14;
        int e = gt & 16383;
        float v = (which ? w2 : w1)[e];
        unsigned short h = __half_as_ushort(__float2half_rn(v));
        if (which) g_w2h[e] = h; else g_w1h[e] = h;
    }

    // ---- phase 1: count + rank (grid-stride) ----
    for (int e = gt; e < E; e += gsz)
        rank[e] = atomicAdd(&cnt[dst[e]], 1);

    // ---- grid barrier ----
    __syncthreads();
    if (tid == 0) {
        __threadfence();
        atomicAdd(sync_ctr, 1);
        while (*((volatile int*)sync_ctr) < nblk) { }
        __threadfence();
    }
    __syncthreads();

    // ---- phase 2: block scan + cross-block offsets (consumes cnt) ----
    int i = gt;
    int v = 0;
    if (i < N) { v = cnt[i]; cnt[i] = 0; }
    s[tid] = v;
    if (tid == 0) boff_sh = 0;
    __syncthreads();
#pragma unroll
    for (int off = 1; off < SCAN_B; off <<= 1) {
        int t = (tid >= off) ? s[tid - off] : 0;
        __syncthreads();
        s[tid] += t;
        __syncthreads();
    }
    if (tid == SCAN_B - 1)
        *((volatile int*)&bsums[b]) = s[tid] | 0x80000000;
    if (tid < b) {
        int bv;
        do { bv = *((volatile int*)&bsums[tid]); } while ((bv & 0x80000000) == 0);
        atomicAdd(&boff_sh, bv & 0x7FFFFFFF);
    }
    __syncthreads();
    if (i < N) {
        int rs = boff_sh + s[tid] - v;
        rc[i] = make_int2(rs, v);
    }
}

// atomic-free fill; also resets bsums + sync counter for the next replay
__global__ void fill_kernel(const int* __restrict__ src, const int* __restrict__ dst,
                            const float* __restrict__ ew,
                            const int2* __restrict__ rc, const int* __restrict__ rank,
                            int2* __restrict__ colw, int* __restrict__ bsums,
                            int* __restrict__ sync_ctr, int E) {
    if (blockIdx.x == 0) {
        if (threadIdx.x < MAXBLK) bsums[threadIdx.x] = 0;
        if (threadIdx.x == 0) *sync_ctr = 0;
    }
    int e = blockIdx.x * blockDim.x + threadIdx.x;
    if (e < E) {
        int d = dst[e];
        int pos = __ldg(&rc[d]).x + rank[e];
        colw[pos] = make_int2(src[e], __float_as_int(ew[e]));
    }
}

// ---------------------------------------------------------------------------
// aggregation + combine:  y = (1+eps)*x + mean over in-edges of x[src]*w
// ---------------------------------------------------------------------------
__global__ void __launch_bounds__(256)
agg_kernel(const float* __restrict__ x,
           const int2* __restrict__ rc, const int2* __restrict__ colw,
           const float* __restrict__ eps_ptr, int eps_idx,
           float* __restrict__ y, int N) {
    int t = blockIdx.x * blockDim.x + threadIdx.x;
    int node = t >> 5;
    int lane = t & 31;
    if (node >= N) return;

    int2 rcv = __ldg(&rc[node]);
    int start = rcv.x;
    int c = rcv.y;

    float4 a0 = make_float4(0.f, 0.f, 0.f, 0.f);
    float4 a1 = a0;
    int j = 0;
    for (; j + 1 < c; j += 2) {
        int2 e0 = __ldg(&colw[start + j]);
        int2 e1 = __ldg(&colw[start + j + 1]);
        float w0 = __int_as_float(e0.y);
        float w1 = __int_as_float(e1.y);
        float4 v0 = __ldg(reinterpret_cast<const float4*>(x + (size_t)e0.x * DHID) + lane);
        float4 v1 = __ldg(reinterpret_cast<const float4*>(x + (size_t)e1.x * DHID) + lane);
        a0.x += v0.x * w0; a0.y += v0.y * w0; a0.z += v0.z * w0; a0.w += v0.w * w0;
        a1.x += v1.x * w1; a1.y += v1.y * w1; a1.z += v1.z * w1; a1.w += v1.w * w1;
    }
    if (j < c) {
        int2 e0 = __ldg(&colw[start + j]);
        float w0 = __int_as_float(e0.y);
        float4 v0 = __ldg(reinterpret_cast<const float4*>(x + (size_t)e0.x * DHID) + lane);
        a0.x += v0.x * w0; a0.y += v0.y * w0; a0.z += v0.z * w0; a0.w += v0.w * w0;
    }
    float dinv = (c > 0) ? (1.0f / (float)c) : 0.0f;
    float epsv = 1.0f + eps_ptr[eps_idx];

    float4 xv = __ldg(reinterpret_cast<const float4*>(x + (size_t)node * DHID + lane * 4));
    float4 o;
    o.x = epsv * xv.x + (a0.x + a1.x) * dinv;
    o.y = epsv * xv.y + (a0.y + a1.y) * dinv;
    o.z = epsv * xv.z + (a0.z + a1.z) * dinv;
    o.w = epsv * xv.w + (a0.w + a1.w) * dinv;
    *reinterpret_cast<float4*>(y + (size_t)node * DHID + lane * 4) = o;
}

// ---------------------------------------------------------------------------
// HMMA GEMM (fp16 2-term):  out = y @ W^T + b  [+relu]
//   A = Ahi + Alo (fp16 split, effectively exact), B = fp16(W)
//   D = Ahi*Bhi + Alo*Bhi  (B-rounding error ~1e-4, threshold 1e-3)
// 64-row tiles; smem 69632B -> 3 CTAs/SM (24 warps, was 16).
// Mainloop per thread per k-step: 24 LDS + 16 HMMA (was 40 + 24).
// ---------------------------------------------------------------------------
#define PADB 272
#define SM_A_HI 0
#define SM_A_LO 17408
#define SM_B    34816
#define SM_TOT  69632

__global__ void __launch_bounds__(256, 3)
mm_kernel(const float* __restrict__ y,
          const unsigned short* __restrict__ wh,
          const float* __restrict__ b,
          float* __restrict__ out, int n_rows, int do_relu, int zero_row0) {
    extern __shared__ __align__(16) char sm[];
    int tid = threadIdx.x;
    int lane = tid & 31;
    int wid = tid >> 5;

    // copy W hi (128 rows x 128 fp16) into padded smem
    {
        const uint4* bh = reinterpret_cast<const uint4*>(wh);
#pragma unroll
        for (int i = 0; i < 8; i++) {
            int idx = tid + i * 256;
            int row = idx >> 4;
            int c = idx & 15;
            *reinterpret_cast<uint4*>(sm + SM_B + row * PADB + c * 16) = bh[idx];
        }
    }

    int row0 = blockIdx.x * 64;
    {
        int r = tid >> 2;               // 0..63
        int kb = (tid & 3) * 32;        // 0,32,64,96
        int grow = row0 + r;
        bool valid = (grow < n_rows);
        const float4* yp = reinterpret_cast<const float4*>(y + (size_t)grow * 128 + kb);
#pragma unroll
        for (int j = 0; j < 8; j++) {
            float4 v = valid ? __ldg(yp + j) : make_float4(0.f, 0.f, 0.f, 0.f);
            float r0, r1, r2, r3;
            uint2 hp, lp;
            hp.x = pack_h2(v.x, v.y, r0, r1);
            hp.y = pack_h2(v.z, v.w, r2, r3);
            lp.x = pack_h2n(r0, r1);
            lp.y = pack_h2n(r2, r3);
            uint32_t off = (uint32_t)(r * PADB + (kb + j * 4) * 2);
            *reinterpret_cast<uint2*>(sm + SM_A_HI + off) = hp;
            *reinterpret_cast<uint2*>(sm + SM_A_LO + off) = lp;
        }
    }
    __syncthreads();

    int gid = lane >> 2;
    int tig = lane & 3;
    int wr = (wid & 3) * 16;   // warp row base
    int wn = (wid >> 2) * 64;  // warp col base

    const char* pAhi = sm + SM_A_HI + (wr + gid) * PADB + tig * 4;
    const char* pAlo = sm + SM_A_LO + (wr + gid) * PADB + tig * 4;
    const char* pB   = sm + SM_B    + (wn + gid) * PADB + tig * 4;

    float acc[8][4];
#pragma unroll
    for (int nt = 0; nt < 8; nt++)
#pragma unroll
        for (int q = 0; q < 4; q++) acc[nt][q] = 0.f;

#pragma unroll
    for (int k = 0; k < 8; k++) {
        int ko = k * 32;
        uint32_t ahi[4], alo[4];
        ahi[0] = *reinterpret_cast<const uint32_t*>(pAhi + ko);
        ahi[1] = *reinterpret_cast<const uint32_t*>(pAhi + 8 * PADB + ko);
        ahi[2] = *reinterpret_cast<const uint32_t*>(pAhi + ko + 16);
        ahi[3] = *reinterpret_cast<const uint32_t*>(pAhi + 8 * PADB + ko + 16);
        alo[0] = *reinterpret_cast<const uint32_t*>(pAlo + ko);
        alo[1] = *reinterpret_cast<const uint32_t*>(pAlo + 8 * PADB + ko);
        alo[2] = *reinterpret_cast<const uint32_t*>(pAlo + ko + 16);
        alo[3] = *reinterpret_cast<const uint32_t*>(pAlo + 8 * PADB + ko + 16);
#pragma unroll
        for (int nt = 0; nt < 8; nt++) {
            int no = nt * 8 * PADB;
            uint32_t bh[2];
            bh[0] = *reinterpret_cast<const uint32_t*>(pB + no + ko);
            bh[1] = *reinterpret_cast<const uint32_t*>(pB + no + ko + 16);
            mma_f16(acc[nt], ahi, bh);
            mma_f16(acc[nt], alo, bh);
        }
    }

#pragma unroll
    for (int nt = 0; nt < 8; nt++) {
        int colc = wn + nt * 8 + tig * 2;
        float2 bv = *reinterpret_cast<const float2*>(b + colc);
        int ra = row0 + wr + gid;
        float2 o0, o1;
        o0.x = acc[nt][0] + bv.x;
        o0.y = acc[nt][1] + bv.y;
        o1.x = acc[nt][2] + bv.x;
        o1.y = acc[nt][3] + bv.y;
        if (do_relu) {
            o0.x = fmaxf(o0.x, 0.f); o0.y = fmaxf(o0.y, 0.f);
            o1.x = fmaxf(o1.x, 0.f); o1.y = fmaxf(o1.y, 0.f);
        }
        if (zero_row0 && ra == 0) { o0.x = 0.f; o0.y = 0.f; }
        if (ra < n_rows)
            *reinterpret_cast<float2*>(out + (size_t)ra * 128 + colc) = o0;
        if (ra + 8 < n_rows)
            *reinterpret_cast<float2*>(out + (size_t)(ra + 8) * 128 + colc) = o1;
    }
}

// ---------------------------------------------------------------------------
extern "C" void kernel_launch(void* const* d_in, const int* in_sizes, int n_in,
                              void* d_out, int out_size) {
    const float* emb    = (const float*)d_in[0];
    const float* w1     = (const float*)d_in[1];
    const float* b1     = (const float*)d_in[2];
    const float* w2     = (const float*)d_in[3];
    const float* b2     = (const float*)d_in[4];
    const float* eps    = (const float*)d_in[5];
    const float* edge_w = (const float*)d_in[6];
    const int*   src    = (const int*)d_in[7];
    const int*   dst    = (const int*)d_in[8];

    int N = in_sizes[0] / DHID;
    int E = in_sizes[6];
    float* out = (float*)d_out;

    float *x1, *x2;
    int *cnt, *bsums, *rank, *sync_ctr;
    int2 *rc, *colw;
    unsigned short *w1h, *w2h;
    cudaGetSymbolAddress((void**)&x1, g_x1);
    cudaGetSymbolAddress((void**)&x2, g_x2);
    cudaGetSymbolAddress((void**)&cnt, g_cnt);
    cudaGetSymbolAddress((void**)&rc, g_rc);
    cudaGetSymbolAddress((void**)&rank, g_rank);
    cudaGetSymbolAddress((void**)&bsums, g_bsums);
    cudaGetSymbolAddress((void**)&sync_ctr, g_sync);
    cudaGetSymbolAddress((void**)&colw, g_colw);
    cudaGetSymbolAddress((void**)&w1h, g_w1h);
    cudaGetSymbolAddress((void**)&w2h, g_w2h);

    static bool attr_set = false;
    if (!attr_set) {
        cudaFuncSetAttribute(mm_kernel,
                             cudaFuncAttributeMaxDynamicSharedMemorySize, SM_TOT);
        attr_set = true;
    }

    int nb = (N + SCAN_B - 1) / SCAN_B;   // 98 blocks, all co-resident
    int g_edges = (E + 255) / 256;
    int g_agg   = ((size_t)N * 32 + 255) / 256;
    int g_mm    = (N + 63) / 64;

    // ---- CSR build + W prep in ONE kernel; fill resets barrier state ----
    csr_build_kernel<<<nb, SCAN_B>>>(dst, w1, w2, cnt, rank, bsums, sync_ctr,
                                     rc, N, E, nb);                         // 1
    fill_kernel<<<g_edges, 256>>>(src, dst, edge_w, rc, rank, colw,
                                  bsums, sync_ctr, E);                      // 2

    // ---- layer 1 ----
    agg_kernel<<<g_agg, 256>>>(emb, rc, colw, eps, 0, x2, N);               // 3
    mm_kernel<<<g_mm, 256, SM_TOT>>>(x2, w1h, b1, x1, N, 1, 0);             // 4 <- ncu

    // ---- layer 2 ----
    agg_kernel<<<g_agg, 256>>>(x1, rc, colw, eps, 1, x2, N);
    mm_kernel<<<g_mm, 256, SM_TOT>>>(x2, w2h, b2, x1, N, 1, 0);

    // ---- layer 3 ----
    agg_kernel<<<g_agg, 256>>>(x1, rc, colw, eps, 2, x2, N);
    mm_kernel<<<g_mm, 256, SM_TOT>>>(x2, w2h, b2, out, N, 0, 1);
}